// round 14
// baseline (speedup 1.0000x reference)
#include <cuda_runtime.h>
#include <cuda_fp16.h>
#include <cstdint>

// Problem constants (fixed shapes)
#define Bc    128
#define Nc    512
#define Kc    12
#define DIMc  128
#define BN_TOTAL (Bc * Nc)

// Scratch for aggregated neighbor features [B*N, DIM]
__device__ __align__(16) float g_agg[(size_t)BN_TOTAL * DIMc];

// ---------- mma.sync + cp.async helpers (sm_80-compatible PTX) ----------
__device__ __forceinline__ void mma16816(float (&c)[4],
                                         uint32_t a0, uint32_t a1, uint32_t a2, uint32_t a3,
                                         uint32_t b0, uint32_t b1) {
    asm volatile(
        "mma.sync.aligned.m16n8k16.row.col.f32.f16.f16.f32 "
        "{%0,%1,%2,%3}, {%4,%5,%6,%7}, {%8,%9}, {%0,%1,%2,%3};"
        : "+f"(c[0]), "+f"(c[1]), "+f"(c[2]), "+f"(c[3])
        : "r"(a0), "r"(a1), "r"(a2), "r"(a3), "r"(b0), "r"(b1));
}
__device__ __forceinline__ void cp16(uint32_t saddr, const void* gptr) {
    asm volatile("cp.async.cg.shared.global [%0], [%1], 16;"
                 :: "r"(saddr), "l"(gptr));
}
#define CP_COMMIT() asm volatile("cp.async.commit_group;" ::: "memory")
#define CP_WAIT1()  asm volatile("cp.async.wait_group 1;" ::: "memory")

__device__ __forceinline__ uint32_t packh(float v0, float v1) {
    __half2 hh = __floats2half2_rn(v0, v1);
    return *(uint32_t*)&hh;
}

// ---------------- attn kernel smem layout ----------------
#define ATTN_GRID     148
#define ATTN_WARPS    12
#define ATTN_THREADS  (ATTN_WARPS * 32)
#define TOTAL_WARPS   (ATTN_GRID * ATTN_WARPS)
#define BF_U4_STRIDE  20                         // uint4 per d-row (conflict-free)
#define BF_BYTES      (128 * BF_U4_STRIDE * 16)  // 40960
#define SL_WORDS      1744                       // per warp-slice (fp32 words)
#define SL_NBR_STRIDE 132
#define SL_EXTRA      1584
#define SL_W          1712
#define SL_LG         1728
#define SMEM1_BYTES   (BF_BYTES + 2 * ATTN_WARPS * SL_WORDS * 4 + 2 * 128 * 4)  // 209408

__device__ __forceinline__ void issue_bn(uint32_t sa, const float* nbrv,
                                         const float* nbrw, const float* extra,
                                         int bn, int lane) {
    const char* nb = (const char*)(nbrv + (size_t)bn * (Kc * DIMc));
#pragma unroll
    for (int r = 0; r < 12; r++)
        cp16(sa + (uint32_t)(r * SL_NBR_STRIDE + lane * 4) * 4, nb + r * 512 + lane * 16);
    cp16(sa + (uint32_t)(SL_EXTRA + lane * 4) * 4,
         (const char*)(extra + (size_t)bn * DIMc) + lane * 16);
    if (lane < 3)
        cp16(sa + (uint32_t)(SL_W + lane * 4) * 4,
             (const char*)(nbrw + (size_t)bn * Kc) + lane * 16);
}

// =====================================================================
// Kernel 1: fp16 1-term mma.sync attention + softmax + aggregation.
//   148 CTAs x 384 threads (12 warps = 3/SMSP); warp-per-bn with
//   double-buffered cp.async slices (refill issued at iteration start
//   -> DRAM latency fully hidden).
//   D[k,d] = fp16(en) @ fp16(W1); B table packs ks-pairs per uint4
//   (stride 20 -> conflict-free LDS.128 feeding 2 mma). Epilogue adds
//   wk*W1[128,d] (fp32), lrelu, dot w2, softmax, fp32 aggregation.
// =====================================================================
__global__ __launch_bounds__(ATTN_THREADS, 1)
void attn_kernel(const float* __restrict__ nbrv,   // [B,N,K,DIM]
                 const float* __restrict__ nbrw,   // [B,N,K]
                 const float* __restrict__ extra,  // [B,N,DIM]
                 const float* __restrict__ w1,     // [129,128]
                 const float* __restrict__ w2p)    // [128,1]
{
    extern __shared__ __align__(16) float smem[];
    uint4* BF      = (uint4*)smem;                     // [128][20] uint4
    float* slices  = smem + BF_BYTES / 4;              // 24 warp-slices (2 per warp)
    float* w2_s    = slices + 2 * ATTN_WARPS * SL_WORDS;
    float* w1r_s   = w2_s + 128;

    const int t = threadIdx.x, warp = t >> 5, lane = t & 31;
    const int g = lane >> 2, tc = lane & 3;

    // ---- one-time: W1 fragment table, fp16, ks-pairs packed ----
#pragma unroll
    for (int i = 0; i < 6; i++) {
        int idx = t + i * ATTN_THREADS;        // 2048 entries = d*16 + ks2*4 + tc
        if (idx < 2048) {
            int d = idx >> 4, rem = idx & 15, ks2 = rem >> 2, tcc = rem & 3;
            int jA = 32 * ks2 + 2 * tcc;       // ks = 2*ks2
            int jB = jA + 16;                  // ks = 2*ks2+1
            uint32_t b0A = packh(w1[jA * 128 + d],       w1[(jA + 1) * 128 + d]);
            uint32_t b1A = packh(w1[(jA + 8) * 128 + d], w1[(jA + 9) * 128 + d]);
            uint32_t b0B = packh(w1[jB * 128 + d],       w1[(jB + 1) * 128 + d]);
            uint32_t b1B = packh(w1[(jB + 8) * 128 + d], w1[(jB + 9) * 128 + d]);
            BF[d * BF_U4_STRIDE + ks2 * 4 + tcc] = make_uint4(b0A, b1A, b0B, b1B);
        }
    }
    if (t < 128) { w2_s[t] = w2p[t]; w1r_s[t] = w1[128 * 128 + t]; }
    __syncthreads();

    float* sl0 = slices + (warp * 2 + 0) * SL_WORDS;
    float* sl1 = slices + (warp * 2 + 1) * SL_WORDS;
    const uint32_t sa0 = (uint32_t)__cvta_generic_to_shared(sl0);
    const uint32_t sa1 = (uint32_t)__cvta_generic_to_shared(sl1);

    const int gw = blockIdx.x * ATTN_WARPS + warp;

    // prologue: prefetch first bn into buffer 0
    if (gw < BN_TOTAL) issue_bn(sa0, nbrv, nbrw, extra, gw, lane);
    CP_COMMIT();

    int buf = 0;
    for (int bn = gw; bn < BN_TOTAL; bn += TOTAL_WARPS) {
        // prefetch next bn into the other buffer (hidden under this iteration)
        int bnN = bn + TOTAL_WARPS;
        if (bnN < BN_TOTAL)
            issue_bn(buf ? sa0 : sa1, nbrv, nbrw, extra, bnN, lane);
        CP_COMMIT();
        CP_WAIT1();            // current bn's data resident
        __syncwarp();

        const float* sl = buf ? sl1 : sl0;
        const float* nb = sl;
        const float* ex = sl + SL_EXTRA;

        float acc[16][4];
#pragma unroll
        for (int nt = 0; nt < 16; nt++) {
            acc[nt][0] = 0.f; acc[nt][1] = 0.f; acc[nt][2] = 0.f; acc[nt][3] = 0.f;
        }

        const bool hasHi = (g < 4);            // rows g+8 valid only if < 12
#pragma unroll
        for (int ks2 = 0; ks2 < 4; ks2++) {
            uint32_t a[2][4];
#pragma unroll
            for (int s = 0; s < 2; s++) {
                const int jb = 32 * ks2 + 16 * s + 2 * tc;
                float2 e0 = *(const float2*)(ex + jb);
                float2 e1 = *(const float2*)(ex + jb + 8);
                float2 p00 = *(const float2*)(nb + g * SL_NBR_STRIDE + jb);
                float2 p01 = *(const float2*)(nb + g * SL_NBR_STRIDE + jb + 8);
                float2 p10 = make_float2(0.f, 0.f), p11 = make_float2(0.f, 0.f);
                if (hasHi) {
                    p10 = *(const float2*)(nb + (g + 8) * SL_NBR_STRIDE + jb);
                    p11 = *(const float2*)(nb + (g + 8) * SL_NBR_STRIDE + jb + 8);
                }
                a[s][0] = packh(e0.x * p00.x, e0.y * p00.y);
                a[s][1] = packh(e0.x * p10.x, e0.y * p10.y);
                a[s][2] = packh(e1.x * p01.x, e1.y * p01.y);
                a[s][3] = packh(e1.x * p11.x, e1.y * p11.y);
            }
            const uint4* brow = BF + ks2 * 4 + tc;
#pragma unroll
            for (int nt = 0; nt < 16; nt++) {
                uint4 b = brow[(nt * 8 + g) * BF_U4_STRIDE];
                mma16816(acc[nt], a[0][0], a[0][1], a[0][2], a[0][3], b.x, b.y);
                mma16816(acc[nt], a[1][0], a[1][1], a[1][2], a[1][3], b.z, b.w);
            }
        }

        // ---- epilogue: logits ----
        const float wg  = sl[SL_W + g];
        const float wg8 = sl[SL_W + g + 8];   // garbage for g>=4 -> rows discarded
        float pg = 0.f, pg8 = 0.f;
#pragma unroll
        for (int nt = 0; nt < 16; nt++) {
            int d0 = nt * 8 + 2 * tc;
            float2 w2v = *(const float2*)(w2_s + d0);
            float2 wrv = *(const float2*)(w1r_s + d0);
            float x;
            x = acc[nt][0] + wg  * wrv.x; pg  += w2v.x * ((x > 0.f) ? x : 0.2f * x);
            x = acc[nt][1] + wg  * wrv.y; pg  += w2v.y * ((x > 0.f) ? x : 0.2f * x);
            x = acc[nt][2] + wg8 * wrv.x; pg8 += w2v.x * ((x > 0.f) ? x : 0.2f * x);
            x = acc[nt][3] + wg8 * wrv.y; pg8 += w2v.y * ((x > 0.f) ? x : 0.2f * x);
        }
        pg  += __shfl_xor_sync(0xffffffffu, pg, 1);
        pg  += __shfl_xor_sync(0xffffffffu, pg, 2);
        pg8 += __shfl_xor_sync(0xffffffffu, pg8, 1);
        pg8 += __shfl_xor_sync(0xffffffffu, pg8, 2);
        float* slw = (float*)sl;
        if (tc == 0) { slw[SL_LG + g] = pg; slw[SL_LG + g + 8] = pg8; }
        __syncwarp();

        // ---- softmax over k=0..11 (all lanes redundantly) ----
        float lg[12];
        float m = -1e30f;
#pragma unroll
        for (int k = 0; k < 12; k++) { lg[k] = sl[SL_LG + k]; m = fmaxf(m, lg[k]); }
        float ssum = 0.f;
#pragma unroll
        for (int k = 0; k < 12; k++) { lg[k] = __expf(lg[k] - m); ssum += lg[k]; }
        const float inv = 1.0f / ssum;

        // ---- aggregation: lane covers d = lane*4..+3 (fp32 exact) ----
        float4 a4 = make_float4(0.f, 0.f, 0.f, 0.f);
#pragma unroll
        for (int k = 0; k < 12; k++) {
            float al = lg[k] * inv;
            float4 nv = *(const float4*)(nb + k * SL_NBR_STRIDE + lane * 4);
            a4.x = fmaf(al, nv.x, a4.x);
            a4.y = fmaf(al, nv.y, a4.y);
            a4.z = fmaf(al, nv.z, a4.z);
            a4.w = fmaf(al, nv.w, a4.w);
        }
        *(float4*)(g_agg + (size_t)bn * DIMc + lane * 4) = a4;

        buf ^= 1;
        __syncwarp();          // all lanes done with this buffer before reuse
    }
}

// =====================================================================
// Kernel 2: out = relu(concat(self, agg) @ W3) via fp16 1-term mma.
//   292 CTAs x 256 threads -> 2 CTAs/SM on nearly all SMs; the two
//   resident CTAs drift out of phase so one CTA's staging hides the
//   other's mma. Pass = 64 rows: warp = (rowgroup rg 0..3, colhalf ch).
//   W3 table packs ks-pairs per uint4 (stride 36, conflict-free).
// =====================================================================
#define OUT_GRID      292
#define OUT_THREADS   256
#define BF3_U4_STRIDE 36
#define BF3_BYTES     (128 * BF3_U4_STRIDE * 16)     // 73728
#define XH_STRIDE     132                            // u32 words per row
#define XH_WORDS      (16 * XH_STRIDE)               // per rowgroup
#define SMEM2_BYTES   (BF3_BYTES + 4 * XH_WORDS * 4) // 73728+33792=107520

__global__ __launch_bounds__(OUT_THREADS, 2)
void out_kernel(const float* __restrict__ selfv,  // [B,N,DIM]
                const float* __restrict__ w3,     // [256,128]
                float* __restrict__ out)          // [B,N,DIM]
{
    extern __shared__ __align__(16) float smem[];
    uint4*    BF3 = (uint4*)smem;
    uint32_t* xh  = (uint32_t*)(smem + BF3_BYTES / 4);

    const int t = threadIdx.x, warp = t >> 5, lane = t & 31;
    const int g = lane >> 2, tc = lane & 3;
    const int rg = warp >> 1, ch = warp & 1;
    const int pairlane = t & 63;

    // ---- one-time: W3 fragment table (fp16, ks-pairs packed) ----
#pragma unroll
    for (int i = 0; i < 16; i++) {
        int idx = t + i * OUT_THREADS;         // 4096 entries = d*32 + ks2*4 + tc
        int d = idx >> 5, rem = idx & 31, ks2 = rem >> 2, tcc = rem & 3;
        int jA = 32 * ks2 + 2 * tcc;           // ks = 2*ks2
        int jB = jA + 16;                      // ks = 2*ks2+1
        uint32_t b0A = packh(w3[jA * 128 + d],       w3[(jA + 1) * 128 + d]);
        uint32_t b1A = packh(w3[(jA + 8) * 128 + d], w3[(jA + 9) * 128 + d]);
        uint32_t b0B = packh(w3[jB * 128 + d],       w3[(jB + 1) * 128 + d]);
        uint32_t b1B = packh(w3[(jB + 8) * 128 + d], w3[(jB + 9) * 128 + d]);
        BF3[d * BF3_U4_STRIDE + ks2 * 4 + tcc] = make_uint4(b0A, b1A, b0B, b1B);
    }
    __syncthreads();

    uint32_t* xw = xh + rg * XH_WORDS;
    const int n_pass = BN_TOTAL / 64;         // 1024

    for (int p = blockIdx.x; p < n_pass; p += gridDim.x) {
        const int row0 = p * 64 + rg * 16;     // this rowgroup's 16 rows

        // ---- stage x = concat(self, agg) as fp16 (warp pair, 64 lanes) ----
        // 16 rows x 64 float4 = 1024 f4; 16 per lane
#pragma unroll
        for (int i = 0; i < 16; i++) {
            int idx = i * 64 + pairlane;
            int row = idx >> 6, f4 = idx & 63;
            const float4 v = (f4 < 32)
                ? *(const float4*)(selfv + (size_t)(row0 + row) * 128 + f4 * 4)
                : *(const float4*)(g_agg + (size_t)(row0 + row) * 128 + (f4 - 32) * 4);
            uint2 w2v;
            w2v.x = packh(v.x, v.y);
            w2v.y = packh(v.z, v.w);
            *(uint2*)(xw + row * XH_STRIDE + f4 * 2) = w2v;
        }
        __syncthreads();

        float acc[8][4];
#pragma unroll
        for (int nt = 0; nt < 8; nt++) {
            acc[nt][0] = 0.f; acc[nt][1] = 0.f; acc[nt][2] = 0.f; acc[nt][3] = 0.f;
        }

#pragma unroll
        for (int ks2 = 0; ks2 < 8; ks2++) {
            uint32_t a[2][4];
#pragma unroll
            for (int s = 0; s < 2; s++) {
                int ks = 2 * ks2 + s;
                a[s][0] = xw[g * XH_STRIDE + 8 * ks + tc];
                a[s][1] = xw[(g + 8) * XH_STRIDE + 8 * ks + tc];
                a[s][2] = xw[g * XH_STRIDE + 8 * ks + tc + 4];
                a[s][3] = xw[(g + 8) * XH_STRIDE + 8 * ks + tc + 4];
            }
            const uint4* brow = BF3 + ks2 * 4 + tc;
#pragma unroll
            for (int nt = 0; nt < 8; nt++) {
                uint4 b = brow[(ch * 64 + nt * 8 + g) * BF3_U4_STRIDE];
                mma16816(acc[nt], a[0][0], a[0][1], a[0][2], a[0][3], b.x, b.y);
                mma16816(acc[nt], a[1][0], a[1][1], a[1][2], a[1][3], b.z, b.w);
            }
        }

        // ---- epilogue: relu + store (warp's 64-col half) ----
#pragma unroll
        for (int nt = 0; nt < 8; nt++) {
            int d0 = ch * 64 + nt * 8 + 2 * tc;
            float2 v0 = make_float2(fmaxf(acc[nt][0], 0.f), fmaxf(acc[nt][1], 0.f));
            float2 v1 = make_float2(fmaxf(acc[nt][2], 0.f), fmaxf(acc[nt][3], 0.f));
            *(float2*)(out + (size_t)(row0 + g) * 128 + d0)     = v0;
            *(float2*)(out + (size_t)(row0 + g + 8) * 128 + d0) = v1;
        }
        __syncthreads();   // xw reuse next pass
    }
}

// =====================================================================
// Launch.  Inputs: 0 self, 1 neighbor_vector, 2 neighbor_weight,
//   3 extra_vector, 4 masks, 5 batch_size, 6 w_1, 7 w_2, 8 w_3
// =====================================================================
extern "C" void kernel_launch(void* const* d_in, const int* in_sizes, int n_in,
                              void* d_out, int out_size)
{
    const float* selfv = (const float*)d_in[0];
    const float* nbrv  = (const float*)d_in[1];
    const float* nbrw  = (const float*)d_in[2];
    const float* extra = (const float*)d_in[3];
    const float* w1    = (const float*)d_in[6];
    const float* w2    = (const float*)d_in[7];
    const float* w3    = (const float*)d_in[8];
    float* out = (float*)d_out;

    cudaFuncSetAttribute(attn_kernel, cudaFuncAttributeMaxDynamicSharedMemorySize,
                         SMEM1_BYTES);
    attn_kernel<<<ATTN_GRID, ATTN_THREADS, SMEM1_BYTES>>>(nbrv, nbrw, extra, w1, w2);

    cudaFuncSetAttribute(out_kernel, cudaFuncAttributeMaxDynamicSharedMemorySize,
                         SMEM2_BYTES);
    out_kernel<<<OUT_GRID, OUT_THREADS, SMEM2_BYTES>>>(selfv, w3, out);
}

// round 15
// speedup vs baseline: 1.1715x; 1.1715x over previous
#include <cuda_runtime.h>
#include <cuda_fp16.h>
#include <cstdint>

// Problem constants (fixed shapes)
#define Bc    128
#define Nc    512
#define Kc    12
#define DIMc  128
#define BN_TOTAL (Bc * Nc)

// Scratch for aggregated neighbor features [B*N, DIM]
__device__ __align__(16) float g_agg[(size_t)BN_TOTAL * DIMc];

// ---------- mma.sync + cp.async helpers (sm_80-compatible PTX) ----------
__device__ __forceinline__ void mma16816(float (&c)[4],
                                         uint32_t a0, uint32_t a1, uint32_t a2, uint32_t a3,
                                         uint32_t b0, uint32_t b1) {
    asm volatile(
        "mma.sync.aligned.m16n8k16.row.col.f32.f16.f16.f32 "
        "{%0,%1,%2,%3}, {%4,%5,%6,%7}, {%8,%9}, {%0,%1,%2,%3};"
        : "+f"(c[0]), "+f"(c[1]), "+f"(c[2]), "+f"(c[3])
        : "r"(a0), "r"(a1), "r"(a2), "r"(a3), "r"(b0), "r"(b1));
}
__device__ __forceinline__ void cp16(uint32_t saddr, const void* gptr) {
    asm volatile("cp.async.cg.shared.global [%0], [%1], 16;"
                 :: "r"(saddr), "l"(gptr));
}
#define CP_COMMIT() asm volatile("cp.async.commit_group;" ::: "memory")
#define CP_WAIT0()  asm volatile("cp.async.wait_group 0;" ::: "memory")

__device__ __forceinline__ uint32_t packh(float v0, float v1) {
    __half2 hh = __floats2half2_rn(v0, v1);
    return *(uint32_t*)&hh;
}

// ---------------- attn kernel smem layout (exact R12 config) ----------------
#define ATTN_GRID     148
#define ATTN_WARPS    16
#define TOTAL_WARPS   (ATTN_GRID * ATTN_WARPS)
#define BF_U4_STRIDE  20                         // uint4 per d-row (conflict-free)
#define BF_BYTES      (128 * BF_U4_STRIDE * 16)  // 40960
#define SL_WORDS      1744                       // per warp-slice (fp32 words)
#define SL_NBR_STRIDE 132
#define SL_EXTRA      1584
#define SL_W          1712
#define SL_LG         1728
#define SMEM1_USED    (BF_BYTES + ATTN_WARPS * SL_WORDS * 4 + 2 * 128 * 4)  // 153600
#define SMEM1_BYTES   ((SMEM1_USED + 1023) & ~1023)                          // 153600

__device__ __forceinline__ void issue_bn(uint32_t sa, const float* nbrv,
                                         const float* nbrw, const float* extra,
                                         int bn, int lane) {
    const char* nb = (const char*)(nbrv + (size_t)bn * (Kc * DIMc));
#pragma unroll
    for (int r = 0; r < 12; r++)
        cp16(sa + (uint32_t)(r * SL_NBR_STRIDE + lane * 4) * 4, nb + r * 512 + lane * 16);
    cp16(sa + (uint32_t)(SL_EXTRA + lane * 4) * 4,
         (const char*)(extra + (size_t)bn * DIMc) + lane * 16);
    if (lane < 3)
        cp16(sa + (uint32_t)(SL_W + lane * 4) * 4,
             (const char*)(nbrw + (size_t)bn * Kc) + lane * 16);
}

// =====================================================================
// Kernel 1: fp16 1-term mma.sync attention + softmax + aggregation.
//   EXACT R12 configuration (best measured: ~150.6us):
//   148 CTAs x 512 threads (16 warps = 4/SMSP); warp-per-bn, single
//   cp.async buffer per warp (cross-warp latency hiding).
// =====================================================================
__global__ __launch_bounds__(512, 1)
void attn_kernel(const float* __restrict__ nbrv,   // [B,N,K,DIM]
                 const float* __restrict__ nbrw,   // [B,N,K]
                 const float* __restrict__ extra,  // [B,N,DIM]
                 const float* __restrict__ w1,     // [129,128]
                 const float* __restrict__ w2p)    // [128,1]
{
    extern __shared__ __align__(16) float smem[];
    uint4* BF      = (uint4*)smem;                     // [128][20] uint4
    float* slices  = smem + BF_BYTES / 4;              // 16 warp-slices
    float* w2_s    = slices + ATTN_WARPS * SL_WORDS;
    float* w1r_s   = w2_s + 128;

    const int t = threadIdx.x, warp = t >> 5, lane = t & 31;
    const int g = lane >> 2, tc = lane & 3;

    // ---- one-time: W1 fragment table, fp16, ks-pairs packed ----
#pragma unroll
    for (int i = 0; i < 4; i++) {
        int idx = t + i * 512;                 // 2048 entries = d*16 + ks2*4 + tc
        int d = idx >> 4, rem = idx & 15, ks2 = rem >> 2, tcc = rem & 3;
        int jA = 32 * ks2 + 2 * tcc;           // ks = 2*ks2
        int jB = jA + 16;                      // ks = 2*ks2+1
        uint32_t b0A = packh(w1[jA * 128 + d],       w1[(jA + 1) * 128 + d]);
        uint32_t b1A = packh(w1[(jA + 8) * 128 + d], w1[(jA + 9) * 128 + d]);
        uint32_t b0B = packh(w1[jB * 128 + d],       w1[(jB + 1) * 128 + d]);
        uint32_t b1B = packh(w1[(jB + 8) * 128 + d], w1[(jB + 9) * 128 + d]);
        BF[d * BF_U4_STRIDE + ks2 * 4 + tcc] = make_uint4(b0A, b1A, b0B, b1B);
    }
    if (t < 128) { w2_s[t] = w2p[t]; w1r_s[t] = w1[128 * 128 + t]; }
    __syncthreads();

    float* sl = slices + warp * SL_WORDS;
    const uint32_t sa = (uint32_t)__cvta_generic_to_shared(sl);

    const int gw = blockIdx.x * ATTN_WARPS + warp;

    if (gw < BN_TOTAL) issue_bn(sa, nbrv, nbrw, extra, gw, lane);
    CP_COMMIT();

    for (int bn = gw; bn < BN_TOTAL; bn += TOTAL_WARPS) {
        CP_WAIT0();
        __syncwarp();

        const float* nb = sl;
        const float* ex = sl + SL_EXTRA;

        float acc[16][4];
#pragma unroll
        for (int nt = 0; nt < 16; nt++) {
            acc[nt][0] = 0.f; acc[nt][1] = 0.f; acc[nt][2] = 0.f; acc[nt][3] = 0.f;
        }

        const bool hasHi = (g < 4);            // rows g+8 valid only if < 12
#pragma unroll
        for (int ks2 = 0; ks2 < 4; ks2++) {
            uint32_t a[2][4];
#pragma unroll
            for (int s = 0; s < 2; s++) {
                const int jb = 32 * ks2 + 16 * s + 2 * tc;
                float2 e0 = *(const float2*)(ex + jb);
                float2 e1 = *(const float2*)(ex + jb + 8);
                float2 p00 = *(const float2*)(nb + g * SL_NBR_STRIDE + jb);
                float2 p01 = *(const float2*)(nb + g * SL_NBR_STRIDE + jb + 8);
                float2 p10 = make_float2(0.f, 0.f), p11 = make_float2(0.f, 0.f);
                if (hasHi) {
                    p10 = *(const float2*)(nb + (g + 8) * SL_NBR_STRIDE + jb);
                    p11 = *(const float2*)(nb + (g + 8) * SL_NBR_STRIDE + jb + 8);
                }
                a[s][0] = packh(e0.x * p00.x, e0.y * p00.y);
                a[s][1] = packh(e0.x * p10.x, e0.y * p10.y);
                a[s][2] = packh(e1.x * p01.x, e1.y * p01.y);
                a[s][3] = packh(e1.x * p11.x, e1.y * p11.y);
            }
            const uint4* brow = BF + ks2 * 4 + tc;
#pragma unroll
            for (int nt = 0; nt < 16; nt++) {
                uint4 b = brow[(nt * 8 + g) * BF_U4_STRIDE];
                mma16816(acc[nt], a[0][0], a[0][1], a[0][2], a[0][3], b.x, b.y);
                mma16816(acc[nt], a[1][0], a[1][1], a[1][2], a[1][3], b.z, b.w);
            }
        }

        // ---- epilogue: logits ----
        const float wg  = sl[SL_W + g];
        const float wg8 = sl[SL_W + g + 8];   // garbage for g>=4 -> rows discarded
        float pg = 0.f, pg8 = 0.f;
#pragma unroll
        for (int nt = 0; nt < 16; nt++) {
            int d0 = nt * 8 + 2 * tc;
            float2 w2v = *(const float2*)(w2_s + d0);
            float2 wrv = *(const float2*)(w1r_s + d0);
            float x;
            x = acc[nt][0] + wg  * wrv.x; pg  += w2v.x * ((x > 0.f) ? x : 0.2f * x);
            x = acc[nt][1] + wg  * wrv.y; pg  += w2v.y * ((x > 0.f) ? x : 0.2f * x);
            x = acc[nt][2] + wg8 * wrv.x; pg8 += w2v.x * ((x > 0.f) ? x : 0.2f * x);
            x = acc[nt][3] + wg8 * wrv.y; pg8 += w2v.y * ((x > 0.f) ? x : 0.2f * x);
        }
        pg  += __shfl_xor_sync(0xffffffffu, pg, 1);
        pg  += __shfl_xor_sync(0xffffffffu, pg, 2);
        pg8 += __shfl_xor_sync(0xffffffffu, pg8, 1);
        pg8 += __shfl_xor_sync(0xffffffffu, pg8, 2);
        if (tc == 0) { sl[SL_LG + g] = pg; sl[SL_LG + g + 8] = pg8; }
        __syncwarp();

        // ---- softmax over k=0..11 (all lanes redundantly) ----
        float lg[12];
        float m = -1e30f;
#pragma unroll
        for (int k = 0; k < 12; k++) { lg[k] = sl[SL_LG + k]; m = fmaxf(m, lg[k]); }
        float ssum = 0.f;
#pragma unroll
        for (int k = 0; k < 12; k++) { lg[k] = __expf(lg[k] - m); ssum += lg[k]; }
        const float inv = 1.0f / ssum;

        // ---- aggregation: lane covers d = lane*4..+3 (fp32 exact) ----
        float4 a4 = make_float4(0.f, 0.f, 0.f, 0.f);
#pragma unroll
        for (int k = 0; k < 12; k++) {
            float al = lg[k] * inv;
            float4 nv = *(const float4*)(nb + k * SL_NBR_STRIDE + lane * 4);
            a4.x = fmaf(al, nv.x, a4.x);
            a4.y = fmaf(al, nv.y, a4.y);
            a4.z = fmaf(al, nv.z, a4.z);
            a4.w = fmaf(al, nv.w, a4.w);
        }
        *(float4*)(g_agg + (size_t)bn * DIMc + lane * 4) = a4;

        __syncwarp();   // all lanes done reading before refill
        int bnN = bn + TOTAL_WARPS;
        if (bnN < BN_TOTAL) issue_bn(sa, nbrv, nbrw, extra, bnN, lane);
        CP_COMMIT();
    }
}

// =====================================================================
// Kernel 2 v3: out = relu(concat(self, agg) @ W3) via fp16 1-term mma,
//   BARRIER-FREE warp streaming. 148 CTAs x 512 threads (16 warps).
//   Warp task = 16 rows x all 128 cols (16 nt -> 64 acc regs).
//   A-frags loaded DIRECTLY from gmem (ks2<4 -> selfv, ks2>=4 -> g_agg)
//   as LDG.64 + in-register packh: no shared x, no STS/LDS, no barriers
//   in the loop -> 16 independent warps self-hide all memory latency.
//   W3 table (stride 36, ks-pairs packed) identical to R12; accumulation
//   order identical -> bit-identical results.
// =====================================================================
#define OUT_GRID        148
#define OUT_THREADS     512
#define OUT_TOTAL_WARPS (OUT_GRID * 16)
#define BF3_U4_STRIDE   36
#define BF3_BYTES       (128 * BF3_U4_STRIDE * 16)   // 73728
#define N_ROWTILES      (BN_TOTAL / 16)              // 4096
#define SMEM2_BYTES     BF3_BYTES

__global__ __launch_bounds__(OUT_THREADS, 1)
void out_kernel(const float* __restrict__ selfv,  // [B,N,DIM]
                const float* __restrict__ w3,     // [256,128]
                float* __restrict__ out)          // [B,N,DIM]
{
    extern __shared__ __align__(16) float smem[];
    uint4* BF3 = (uint4*)smem;

    const int t = threadIdx.x, warp = t >> 5, lane = t & 31;
    const int g = lane >> 2, tc = lane & 3;

    // ---- one-time: W3 fragment table (fp16, ks-pairs packed) ----
#pragma unroll
    for (int i = 0; i < 8; i++) {
        int idx = t + i * OUT_THREADS;         // 4096 entries = d*32 + ks2*4 + tc
        int d = idx >> 5, rem = idx & 31, ks2 = rem >> 2, tcc = rem & 3;
        int jA = 32 * ks2 + 2 * tcc;           // ks = 2*ks2
        int jB = jA + 16;                      // ks = 2*ks2+1
        uint32_t b0A = packh(w3[jA * 128 + d],       w3[(jA + 1) * 128 + d]);
        uint32_t b1A = packh(w3[(jA + 8) * 128 + d], w3[(jA + 9) * 128 + d]);
        uint32_t b0B = packh(w3[jB * 128 + d],       w3[(jB + 1) * 128 + d]);
        uint32_t b1B = packh(w3[(jB + 8) * 128 + d], w3[(jB + 9) * 128 + d]);
        BF3[d * BF3_U4_STRIDE + ks2 * 4 + tcc] = make_uint4(b0A, b1A, b0B, b1B);
    }
    __syncthreads();

    for (int tt = blockIdx.x * 16 + warp; tt < N_ROWTILES; tt += OUT_TOTAL_WARPS) {
        const int row0 = tt * 16;

        float acc[16][4];
#pragma unroll
        for (int nt = 0; nt < 16; nt++) {
            acc[nt][0] = 0.f; acc[nt][1] = 0.f; acc[nt][2] = 0.f; acc[nt][3] = 0.f;
        }

#pragma unroll
        for (int ks2 = 0; ks2 < 8; ks2++) {
            uint32_t a[2][4];
#pragma unroll
            for (int s = 0; s < 2; s++) {
                // x feature column for this frag; ks2<4 -> selfv, else g_agg
                const int j = 32 * ks2 + 16 * s + 2 * tc;
                const float* base = (ks2 < 4)
                    ? (selfv + (size_t)row0 * 128 + j)
                    : (g_agg + (size_t)row0 * 128 + (j - 128));
                float2 p0 = *(const float2*)(base + (size_t)g * 128);
                float2 p1 = *(const float2*)(base + (size_t)(g + 8) * 128);
                float2 p2 = *(const float2*)(base + (size_t)g * 128 + 8);
                float2 p3 = *(const float2*)(base + (size_t)(g + 8) * 128 + 8);
                a[s][0] = packh(p0.x, p0.y);
                a[s][1] = packh(p1.x, p1.y);
                a[s][2] = packh(p2.x, p2.y);
                a[s][3] = packh(p3.x, p3.y);
            }
            const uint4* brow = BF3 + ks2 * 4 + tc;
#pragma unroll
            for (int nt = 0; nt < 16; nt++) {
                uint4 b = brow[(nt * 8 + g) * BF3_U4_STRIDE];
                mma16816(acc[nt], a[0][0], a[0][1], a[0][2], a[0][3], b.x, b.y);
                mma16816(acc[nt], a[1][0], a[1][1], a[1][2], a[1][3], b.z, b.w);
            }
        }

        // ---- epilogue: relu + store (all 128 cols) ----
#pragma unroll
        for (int nt = 0; nt < 16; nt++) {
            int d0 = nt * 8 + 2 * tc;
            float2 v0 = make_float2(fmaxf(acc[nt][0], 0.f), fmaxf(acc[nt][1], 0.f));
            float2 v1 = make_float2(fmaxf(acc[nt][2], 0.f), fmaxf(acc[nt][3], 0.f));
            *(float2*)(out + (size_t)(row0 + g) * 128 + d0)     = v0;
            *(float2*)(out + (size_t)(row0 + g + 8) * 128 + d0) = v1;
        }
    }
}

// =====================================================================
// Launch.  Inputs: 0 self, 1 neighbor_vector, 2 neighbor_weight,
//   3 extra_vector, 4 masks, 5 batch_size, 6 w_1, 7 w_2, 8 w_3
// =====================================================================
extern "C" void kernel_launch(void* const* d_in, const int* in_sizes, int n_in,
                              void* d_out, int out_size)
{
    const float* selfv = (const float*)d_in[0];
    const float* nbrv  = (const float*)d_in[1];
    const float* nbrw  = (const float*)d_in[2];
    const float* extra = (const float*)d_in[3];
    const float* w1    = (const float*)d_in[6];
    const float* w2    = (const float*)d_in[7];
    const float* w3    = (const float*)d_in[8];
    float* out = (float*)d_out;

    cudaFuncSetAttribute(attn_kernel, cudaFuncAttributeMaxDynamicSharedMemorySize,
                         SMEM1_BYTES);
    attn_kernel<<<ATTN_GRID, 512, SMEM1_BYTES>>>(nbrv, nbrw, extra, w1, w2);

    cudaFuncSetAttribute(out_kernel, cudaFuncAttributeMaxDynamicSharedMemorySize,
                         SMEM2_BYTES);
    out_kernel<<<OUT_GRID, OUT_THREADS, SMEM2_BYTES>>>(selfv, w3, out);
}